// round 5
// baseline (speedup 1.0000x reference)
#include <cuda_runtime.h>

#define HWSZ 3136          // 56*56
#define NPOS 25088         // B*H*W
#define WS_STRIDE 196      // padded weight-smem row stride (floats)
#define PSTR 80            // attn smem per-position stride (floats): 320B == 64B mod 128B
#define HALO 96            // 12 x 8 halo positions (8x4 tile)

// ---------------- scratch (no cudaMalloc allowed) ----------------
__device__ float g_qkv[(size_t)NPOS * 192];   // [pos][q(64)|k(64)|v(64)]

__device__ __forceinline__ int refl(int i) {
    return i < 0 ? -i : (i >= 56 ? 110 - i : i);
}
// packed f32x2 helpers (Blackwell; ptxas never emits these from C++)
__device__ __forceinline__ unsigned long long bc2(float x) {
    unsigned long long r;
    asm("mov.b64 %0,{%1,%1};" : "=l"(r) : "f"(x));
    return r;
}
__device__ __forceinline__ unsigned long long pk2(float lo, float hi) {
    unsigned long long r;
    asm("mov.b64 %0,{%1,%2};" : "=l"(r) : "f"(lo), "f"(hi));
    return r;
}
__device__ __forceinline__ void fma2(unsigned long long& d, unsigned long long a,
                                     unsigned long long b) {
    asm("fma.rn.f32x2 %0,%1,%2,%0;" : "+l"(d) : "l"(a), "l"(b));
}
__device__ __forceinline__ float2 up2(unsigned long long v) {
    float2 r;
    asm("mov.b64 {%0,%1},%2;" : "=f"(r.x), "=f"(r.y) : "l"(v));
    return r;
}

// ---------------- kernel 1: q,k,v 1x1 convs (GEMM, f32x2 packed) ----------------
// LDS.64 runs in 16-lane phases; start words 6*og mod 32 (og=0..15) are 16
// distinct even banks -> conflict-free without any swizzle.
__global__ __launch_bounds__(256) void qkv_kernel(
    const float* __restrict__ x,
    const float* __restrict__ w1, const float* __restrict__ b1,
    const float* __restrict__ w2, const float* __restrict__ b2,
    const float* __restrict__ w3, const float* __restrict__ b3) {
    extern __shared__ float sm[];
    float* xs = sm;                          // [64 cin][64 pos]
    float* ws = sm + 4096;                   // [64 cin][WS_STRIDE] holding 192 oc
    float* bs = sm + 4096 + 64 * WS_STRIDE;  // [192]

    const int b = blockIdx.y;
    const int pos0 = blockIdx.x * 64;        // 49 tiles * 64 = 3136 exact
    const int tid = threadIdx.x;

    for (int i = tid; i < 4096; i += 256) {
        int cin = i >> 6, p = i & 63;
        xs[i] = x[((size_t)(b * 64 + cin)) * HWSZ + pos0 + p];
    }
    for (int i = tid; i < 4096; i += 256) {
        int oc = i >> 6, cin = i & 63;
        ws[cin * WS_STRIDE + oc] = w1[i];
        ws[cin * WS_STRIDE + 64 + oc] = w2[i];
        ws[cin * WS_STRIDE + 128 + oc] = w3[i];
    }
    if (tid < 192)
        bs[tid] = (tid < 64) ? b1[tid] : (tid < 128 ? b2[tid - 64] : b3[tid - 128]);
    __syncthreads();

    const int w = tid >> 5;    // warp 0..7 -> 8 positions
    const int og = tid & 31;   // lane -> 6 output chans

    unsigned long long acc[8][3];
#pragma unroll
    for (int p = 0; p < 8; ++p)
#pragma unroll
        for (int q = 0; q < 3; ++q) acc[p][q] = 0ull;

    const float4* xs4 = (const float4*)xs;
#pragma unroll 2
    for (int cin = 0; cin < 64; ++cin) {
        float4 xa = xs4[cin * 16 + w * 2];       // positions 8w..8w+3 (broadcast)
        float4 xb = xs4[cin * 16 + w * 2 + 1];   // positions 8w+4..8w+7
        const float2* wr = (const float2*)(ws + cin * WS_STRIDE + og * 6);
        float2 wa = wr[0], wb = wr[1], wcv = wr[2];
        unsigned long long wq0 = pk2(wa.x, wa.y);
        unsigned long long wq1 = pk2(wb.x, wb.y);
        unsigned long long wq2 = pk2(wcv.x, wcv.y);
        unsigned long long xp[8] = {bc2(xa.x), bc2(xa.y), bc2(xa.z), bc2(xa.w),
                                    bc2(xb.x), bc2(xb.y), bc2(xb.z), bc2(xb.w)};
#pragma unroll
        for (int p = 0; p < 8; ++p) {
            fma2(acc[p][0], xp[p], wq0);
            fma2(acc[p][1], xp[p], wq1);
            fma2(acc[p][2], xp[p], wq2);
        }
    }

    float bl[6];
#pragma unroll
    for (int j = 0; j < 6; ++j) bl[j] = bs[og * 6 + j];

#pragma unroll
    for (int p = 0; p < 8; ++p) {
        float* dst = g_qkv + ((size_t)(b * HWSZ + pos0 + w * 8 + p)) * 192 + og * 6;
        float2 v0 = up2(acc[p][0]);
        float2 v1 = up2(acc[p][1]);
        float2 v2 = up2(acc[p][2]);
        float2 o0 = {v0.x + bl[0], v0.y + bl[1]};
        float2 o1 = {v1.x + bl[2], v1.y + bl[3]};
        float2 o2 = {v2.x + bl[4], v2.y + bl[5]};
        *(float2*)(dst + 0) = o0;
        *(float2*)(dst + 2) = o1;
        *(float2*)(dst + 4) = o2;
    }
}

// ---------------- kernel 2: fused attention + conv branch ----------------
// grid (7,14,8): 8x4 spatial tile, 256 threads: 8 subs/pos x 8 ch each.
// Conv branch fused into the attention tap loops (k,v reuse); q has own pass.
__global__ __launch_bounds__(256, 2) void attn_kernel(
    const float* __restrict__ wp,
    const float* __restrict__ w_fc,
    const float* __restrict__ w_dep,
    const float* __restrict__ b_dep,
    const float* __restrict__ rate1,
    const float* __restrict__ rate2,
    float* __restrict__ out) {
    extern __shared__ float sm[];
    float* qs = sm;                      // [HALO][PSTR]
    float* ks = sm + HALO * PSTR;
    float* vs = sm + 2 * HALO * PSTR;
    float* wf = sm + 3 * HALO * PSTR;    // [3][9][64] folded conv weights

    const int b = blockIdx.z;
    const int ty0 = blockIdx.y * 4;
    const int tx0 = blockIdx.x * 8;
    const int tid = threadIdx.x;

    // fold depthwise-conv weights: wf[c][t][d] = sum_m w_dep[d][m][t]*w_fc[m][c]
    for (int i = tid; i < 1728; i += 256) {
        int c = i / 576, r = i % 576, t = r >> 6, d = r & 63;
        float s = 0.f;
#pragma unroll
        for (int m = 0; m < 9; ++m)
            s += w_dep[(d * 9 + m) * 9 + t] * w_fc[m * 3 + c];
        wf[i] = s;
    }

    // halo load: 96 positions x 192 channels, reflect-padded, f4 coalesced
    for (int i = tid; i < HALO * 48; i += 256) {
        int hpos = i / 48;
        int c4 = i % 48;
        int hy = hpos / 12, hx = hpos % 12;
        int gy = refl(ty0 + hy - 2);
        int gx = refl(tx0 + hx - 2);
        float4 v = *(const float4*)(g_qkv +
            ((size_t)(b * HWSZ + gy * 56 + gx)) * 192 + c4 * 4);
        float* arr = (c4 < 16) ? qs : (c4 < 32 ? ks : vs);
        *(float4*)(arr + hpos * PSTR + (c4 & 15) * 4) = v;
    }
    __syncthreads();

    const int pos = tid >> 3;           // 0..31
    const int s = tid & 7;              // channel sub (interleaved chunks)
    const int ty = pos >> 3, tx = pos & 7;
    const int gy = ty0 + ty, gx = tx0 + tx;
    const int chidx = (ty + 2) * 12 + (tx + 2);
    const int sb = s * 4;

    // q into registers. qr[i*4+j] = channel i*32 + s*4 + j
    float qr[8];
    {
        const float* qb = qs + chidx * PSTR + sb;
#pragma unroll
        for (int i = 0; i < 2; ++i) {
            float4 v = *(const float4*)(qb + i * 32);
            qr[i * 4 + 0] = v.x; qr[i * 4 + 1] = v.y;
            qr[i * 4 + 2] = v.z; qr[i * 4 + 3] = v.w;
        }
    }

    float ocv[8];
#pragma unroll
    for (int d = 0; d < 8; ++d) ocv[d] = 0.f;

    // q part of conv branch (9 taps, zero padding)
#pragma unroll
    for (int t = 0; t < 9; ++t) {
        const int dy = t / 3 - 1, dx = t % 3 - 1;
        if ((unsigned)(gy + dy) < 56u && (unsigned)(gx + dx) < 56u) {
            const float* qp = qs + (chidx + dy * 12 + dx) * PSTR + sb;
            const float* wq = wf + (0 * 9 + t) * 64 + sb;
#pragma unroll
            for (int i = 0; i < 2; ++i) {
                float4 qv = *(const float4*)(qp + i * 32);
                float4 wv = *(const float4*)(wq + i * 32);
                ocv[i * 4 + 0] += wv.x * qv.x; ocv[i * 4 + 1] += wv.y * qv.y;
                ocv[i * 4 + 2] += wv.z * qv.z; ocv[i * 4 + 3] += wv.w * qv.w;
            }
        }
    }

    // 25 window dots + fused k-conv on inner taps
    float acc[25];
#pragma unroll
    for (int j = 0; j < 25; ++j) {
        const int dy = j / 5 - 2, dx = j % 5 - 2;
        const float* kb = ks + (chidx + dy * 12 + dx) * PSTR + sb;
        float4 k0 = *(const float4*)(kb);
        float4 k1 = *(const float4*)(kb + 32);
        acc[j] = qr[0] * k0.x + qr[1] * k0.y + qr[2] * k0.z + qr[3] * k0.w +
                 qr[4] * k1.x + qr[5] * k1.y + qr[6] * k1.z + qr[7] * k1.w;
        if (dy >= -1 && dy <= 1 && dx >= -1 && dx <= 1) {   // compile-time
            if ((unsigned)(gy + dy) < 56u && (unsigned)(gx + dx) < 56u) {
                const int t = (dy + 1) * 3 + (dx + 1);
                const float* wk = wf + (1 * 9 + t) * 64 + sb;
                float4 w0 = *(const float4*)(wk);
                float4 w1v = *(const float4*)(wk + 32);
                ocv[0] += w0.x * k0.x; ocv[1] += w0.y * k0.y;
                ocv[2] += w0.z * k0.z; ocv[3] += w0.w * k0.w;
                ocv[4] += w1v.x * k1.x; ocv[5] += w1v.y * k1.y;
                ocv[6] += w1v.z * k1.z; ocv[7] += w1v.w * k1.w;
            }
        }
    }
    // PE dots: a = q.wp[:,0], bq = q.wp[:,1]  (bp term cancels analytically)
    float a = 0.f, bq = 0.f;
#pragma unroll
    for (int i = 0; i < 2; ++i)
#pragma unroll
        for (int j = 0; j < 4; ++j) {
            int ch = i * 32 + s * 4 + j;
            float2 w = __ldg((const float2*)wp + ch);
            a += qr[i * 4 + j] * w.x;
            bq += qr[i * 4 + j] * w.y;
        }
    // 8-lane butterfly reduce (subs are adjacent lanes)
#pragma unroll
    for (int st = 1; st < 8; st <<= 1) {
#pragma unroll
        for (int j = 0; j < 25; ++j)
            acc[j] += __shfl_xor_sync(0xffffffffu, acc[j], st);
        a += __shfl_xor_sync(0xffffffffu, a, st);
        bq += __shfl_xor_sync(0xffffffffu, bq, st);
    }

    // PE correction + scaling + softmax (over 25 taps)
    const float scaling = 0.125f;        // 64^-0.5
    const float lstep = 2.f / 55.f;
    float mx = -1e30f;
#pragma unroll
    for (int j = 0; j < 25; ++j) {
        int dy = j / 5 - 2, dx = j % 5 - 2;
        int gyj = refl(gy + dy), gxj = refl(gx + dx);
        float t = scaling * (acc[j] + a * ((float)(gx - gxj) * lstep) +
                             bq * ((float)(gy - gyj) * lstep));
        acc[j] = t;
        mx = fmaxf(mx, t);
    }
    float ssum = 0.f;
#pragma unroll
    for (int j = 0; j < 25; ++j) {
        float e = __expf(acc[j] - mx);
        acc[j] = e;
        ssum += e;
    }
    float inv = 1.f / ssum;

    // attention output + fused v-conv on inner taps
    float oa[8];
#pragma unroll
    for (int d = 0; d < 8; ++d) oa[d] = 0.f;
#pragma unroll
    for (int j = 0; j < 25; ++j) {
        const int dy = j / 5 - 2, dx = j % 5 - 2;
        const float w = acc[j];
        const float* vb = vs + (chidx + dy * 12 + dx) * PSTR + sb;
        float4 v0 = *(const float4*)(vb);
        float4 v1 = *(const float4*)(vb + 32);
        oa[0] += w * v0.x; oa[1] += w * v0.y; oa[2] += w * v0.z; oa[3] += w * v0.w;
        oa[4] += w * v1.x; oa[5] += w * v1.y; oa[6] += w * v1.z; oa[7] += w * v1.w;
        if (dy >= -1 && dy <= 1 && dx >= -1 && dx <= 1) {   // compile-time
            if ((unsigned)(gy + dy) < 56u && (unsigned)(gx + dx) < 56u) {
                const int t = (dy + 1) * 3 + (dx + 1);
                const float* wv = wf + (2 * 9 + t) * 64 + sb;
                float4 w0 = *(const float4*)(wv);
                float4 w1v = *(const float4*)(wv + 32);
                ocv[0] += w0.x * v0.x; ocv[1] += w0.y * v0.y;
                ocv[2] += w0.z * v0.z; ocv[3] += w0.w * v0.w;
                ocv[4] += w1v.x * v1.x; ocv[5] += w1v.y * v1.y;
                ocv[6] += w1v.z * v1.z; ocv[7] += w1v.w * v1.w;
            }
        }
    }

    const float r1 = rate1[0];
    const float r2 = rate2[0];
#pragma unroll
    for (int i = 0; i < 2; ++i)
#pragma unroll
        for (int j = 0; j < 4; ++j) {
            int ch = i * 32 + s * 4 + j;
            float res = r1 * (oa[i * 4 + j] * inv) +
                        r2 * (ocv[i * 4 + j] + __ldg(b_dep + ch));
            out[((size_t)(b * 64 + ch) * 56 + gy) * 56 + gx] = res;
        }
}

// ---------------- launch ----------------
extern "C" void kernel_launch(void* const* d_in, const int* in_sizes, int n_in,
                              void* d_out, int out_size) {
    const float* x    = (const float*)d_in[0];
    const float* w1   = (const float*)d_in[1];
    const float* b1   = (const float*)d_in[2];
    const float* w2   = (const float*)d_in[3];
    const float* b2   = (const float*)d_in[4];
    const float* w3   = (const float*)d_in[5];
    const float* b3   = (const float*)d_in[6];
    const float* wp   = (const float*)d_in[7];
    // d_in[8] = bp (cancels analytically)
    const float* w_fc = (const float*)d_in[9];
    const float* w_dep = (const float*)d_in[10];
    const float* b_dep = (const float*)d_in[11];
    const float* rate1 = (const float*)d_in[12];
    const float* rate2 = (const float*)d_in[13];
    float* out = (float*)d_out;

    const int qkv_smem = (4096 + 64 * WS_STRIDE + 192) * 4;
    const int att_smem = (3 * HALO * PSTR + 1728) * 4;
    cudaFuncSetAttribute(qkv_kernel, cudaFuncAttributeMaxDynamicSharedMemorySize, qkv_smem);
    cudaFuncSetAttribute(attn_kernel, cudaFuncAttributeMaxDynamicSharedMemorySize, att_smem);

    qkv_kernel<<<dim3(49, 8), 256, qkv_smem>>>(x, w1, b1, w2, b2, w3, b3);
    attn_kernel<<<dim3(7, 14, 8), 256, att_smem>>>(wp, w_fc, w_dep, b_dep, rate1, rate2, out);
}

// round 7
// speedup vs baseline: 1.1520x; 1.1520x over previous
#include <cuda_runtime.h>

#define HWSZ 3136          // 56*56
#define NPOS 25088         // B*H*W
#define WS_STRIDE 196      // padded weight-smem row stride (floats)
#define PSTR 80            // attn smem per-position stride (floats): 320B == 64B mod 128B
#define HALO 96            // 12 x 8 halo positions (8x4 tile)

// ---------------- scratch (no cudaMalloc allowed) ----------------
__device__ float g_qkv[(size_t)NPOS * 192];   // [pos][q(64)|k(64)|v(64)]
__device__ float g_wfold[1728];               // [3][9][64] folded conv weights

__device__ __forceinline__ int refl(int i) {
    return i < 0 ? -i : (i >= 56 ? 110 - i : i);
}
// packed f32x2 helpers (Blackwell; ptxas never emits these from C++)
__device__ __forceinline__ unsigned long long bc2(float x) {
    unsigned long long r;
    asm("mov.b64 %0,{%1,%1};" : "=l"(r) : "f"(x));
    return r;
}
__device__ __forceinline__ unsigned long long pk2(float lo, float hi) {
    unsigned long long r;
    asm("mov.b64 %0,{%1,%2};" : "=l"(r) : "f"(lo), "f"(hi));
    return r;
}
__device__ __forceinline__ void fma2(unsigned long long& d, unsigned long long a,
                                     unsigned long long b) {
    asm("fma.rn.f32x2 %0,%1,%2,%0;" : "+l"(d) : "l"(a), "l"(b));
}
__device__ __forceinline__ float2 up2(unsigned long long v) {
    float2 r;
    asm("mov.b64 {%0,%1},%2;" : "=f"(r.x), "=f"(r.y) : "l"(v));
    return r;
}

// ---------------- kernel 1: q,k,v 1x1 convs (GEMM, f32x2 packed) ----------------
__global__ __launch_bounds__(256) void qkv_kernel(
    const float* __restrict__ x,
    const float* __restrict__ w1, const float* __restrict__ b1,
    const float* __restrict__ w2, const float* __restrict__ b2,
    const float* __restrict__ w3, const float* __restrict__ b3,
    const float* __restrict__ w_fc, const float* __restrict__ w_dep) {
    extern __shared__ float sm[];
    float* xs = sm;                          // [64 cin][64 pos]
    float* ws = sm + 4096;                   // [64 cin][WS_STRIDE] holding 192 oc
    float* bs = sm + 4096 + 64 * WS_STRIDE;  // [192]

    const int b = blockIdx.y;
    const int pos0 = blockIdx.x * 64;        // 49 tiles * 64 = 3136 exact
    const int tid = threadIdx.x;

    // block (0,0) also folds the depthwise-conv weights for the attn kernel:
    // g_wfold[c][t][d] = sum_m w_dep[d][m][t] * w_fc[m][c]
    if (blockIdx.x == 0 && blockIdx.y == 0) {
        for (int i = tid; i < 1728; i += 256) {
            int c = i / 576, r = i % 576, t = r >> 6, d = r & 63;
            float s = 0.f;
#pragma unroll
            for (int m = 0; m < 9; ++m)
                s += w_dep[(d * 9 + m) * 9 + t] * w_fc[m * 3 + c];
            g_wfold[i] = s;
        }
    }

    for (int i = tid; i < 4096; i += 256) {
        int cin = i >> 6, p = i & 63;
        xs[i] = x[((size_t)(b * 64 + cin)) * HWSZ + pos0 + p];
    }
    for (int i = tid; i < 4096; i += 256) {
        int oc = i >> 6, cin = i & 63;
        ws[cin * WS_STRIDE + oc] = w1[i];
        ws[cin * WS_STRIDE + 64 + oc] = w2[i];
        ws[cin * WS_STRIDE + 128 + oc] = w3[i];
    }
    if (tid < 192)
        bs[tid] = (tid < 64) ? b1[tid] : (tid < 128 ? b2[tid - 64] : b3[tid - 128]);
    __syncthreads();

    const int w = tid >> 5;    // warp 0..7 -> 8 positions
    const int og = tid & 31;   // lane -> 6 output chans

    unsigned long long acc[8][3];
#pragma unroll
    for (int p = 0; p < 8; ++p)
#pragma unroll
        for (int q = 0; q < 3; ++q) acc[p][q] = 0ull;

    const float4* xs4 = (const float4*)xs;
#pragma unroll 2
    for (int cin = 0; cin < 64; ++cin) {
        float4 xa = xs4[cin * 16 + w * 2];       // positions 8w..8w+3 (broadcast)
        float4 xb = xs4[cin * 16 + w * 2 + 1];   // positions 8w+4..8w+7
        const float2* wr = (const float2*)(ws + cin * WS_STRIDE + og * 6);
        float2 wa = wr[0], wb = wr[1], wcv = wr[2];
        unsigned long long wq0 = pk2(wa.x, wa.y);
        unsigned long long wq1 = pk2(wb.x, wb.y);
        unsigned long long wq2 = pk2(wcv.x, wcv.y);
        unsigned long long xp[8] = {bc2(xa.x), bc2(xa.y), bc2(xa.z), bc2(xa.w),
                                    bc2(xb.x), bc2(xb.y), bc2(xb.z), bc2(xb.w)};
#pragma unroll
        for (int p = 0; p < 8; ++p) {
            fma2(acc[p][0], xp[p], wq0);
            fma2(acc[p][1], xp[p], wq1);
            fma2(acc[p][2], xp[p], wq2);
        }
    }

    float bl[6];
#pragma unroll
    for (int j = 0; j < 6; ++j) bl[j] = bs[og * 6 + j];

#pragma unroll
    for (int p = 0; p < 8; ++p) {
        float* dst = g_qkv + ((size_t)(b * HWSZ + pos0 + w * 8 + p)) * 192 + og * 6;
        float2 v0 = up2(acc[p][0]);
        float2 v1 = up2(acc[p][1]);
        float2 v2 = up2(acc[p][2]);
        float2 o0 = {v0.x + bl[0], v0.y + bl[1]};
        float2 o1 = {v1.x + bl[2], v1.y + bl[3]};
        float2 o2 = {v2.x + bl[4], v2.y + bl[5]};
        *(float2*)(dst + 0) = o0;
        *(float2*)(dst + 2) = o1;
        *(float2*)(dst + 4) = o2;
    }
}

// ---------------- kernel 2: fused attention + conv branch ----------------
// grid (7,14,8): 8x4 spatial tile, 256 threads: 8 subs/pos x 8 ch each.
// Distributed-tap softmax: lane s of each 8-lane group owns taps j%8==s,
// so PE/exp/normalize are computed once per tap (not 8x redundantly).
__global__ __launch_bounds__(256, 2) void attn_kernel(
    const float* __restrict__ wp,
    const float* __restrict__ b_dep,
    const float* __restrict__ rate1,
    const float* __restrict__ rate2,
    float* __restrict__ out) {
    extern __shared__ float sm[];
    float* qs = sm;                      // [HALO][PSTR]
    float* ks = sm + HALO * PSTR;
    float* vs = sm + 2 * HALO * PSTR;
    float* wf = sm + 3 * HALO * PSTR;    // [3][9][64] folded conv weights

    const int b = blockIdx.z;
    const int ty0 = blockIdx.y * 4;
    const int tx0 = blockIdx.x * 8;
    const int tid = threadIdx.x;

    for (int i = tid; i < 1728; i += 256) wf[i] = g_wfold[i];

    // halo load: 96 positions x 192 channels, reflect-padded, f4 coalesced
    for (int i = tid; i < HALO * 48; i += 256) {
        int hpos = i / 48;
        int c4 = i % 48;
        int hy = hpos / 12, hx = hpos % 12;
        int gy = refl(ty0 + hy - 2);
        int gx = refl(tx0 + hx - 2);
        float4 v = *(const float4*)(g_qkv +
            ((size_t)(b * HWSZ + gy * 56 + gx)) * 192 + c4 * 4);
        float* arr = (c4 < 16) ? qs : (c4 < 32 ? ks : vs);
        *(float4*)(arr + hpos * PSTR + (c4 & 15) * 4) = v;
    }
    __syncthreads();

    const int pos = tid >> 3;           // 0..31
    const int s = tid & 7;              // channel sub / tap owner
    const int ty = pos >> 3, tx = pos & 7;
    const int gy = ty0 + ty, gx = tx0 + tx;
    const int chidx = (ty + 2) * 12 + (tx + 2);
    const int sb = s * 4;

    // q into registers. qr[i*4+j] = channel i*32 + s*4 + j
    float qr[8];
    {
        const float* qb = qs + chidx * PSTR + sb;
        float4 v0 = *(const float4*)(qb);
        float4 v1 = *(const float4*)(qb + 32);
        qr[0] = v0.x; qr[1] = v0.y; qr[2] = v0.z; qr[3] = v0.w;
        qr[4] = v1.x; qr[5] = v1.y; qr[6] = v1.z; qr[7] = v1.w;
    }

    float ocv[8];
#pragma unroll
    for (int d = 0; d < 8; ++d) ocv[d] = 0.f;

    // q part of conv branch (9 taps, zero padding)
#pragma unroll
    for (int t = 0; t < 9; ++t) {
        const int dy = t / 3 - 1, dx = t % 3 - 1;
        if ((unsigned)(gy + dy) < 56u && (unsigned)(gx + dx) < 56u) {
            const float* qp = qs + (chidx + dy * 12 + dx) * PSTR + sb;
            const float* wq = wf + (0 * 9 + t) * 64 + sb;
            float4 qv0 = *(const float4*)(qp), qv1 = *(const float4*)(qp + 32);
            float4 wv0 = *(const float4*)(wq), wv1 = *(const float4*)(wq + 32);
            ocv[0] += wv0.x * qv0.x; ocv[1] += wv0.y * qv0.y;
            ocv[2] += wv0.z * qv0.z; ocv[3] += wv0.w * qv0.w;
            ocv[4] += wv1.x * qv1.x; ocv[5] += wv1.y * qv1.y;
            ocv[6] += wv1.z * qv1.z; ocv[7] += wv1.w * qv1.w;
        }
    }

    // phase 1: 25 window dots, reduced immediately; lane s keeps taps j%8==s.
    float attp[4] = {0.f, 0.f, 0.f, 0.f};
#pragma unroll
    for (int j = 0; j < 25; ++j) {
        const int dy = j / 5 - 2, dx = j % 5 - 2;
        const float* kb = ks + (chidx + dy * 12 + dx) * PSTR + sb;
        float4 k0 = *(const float4*)(kb);
        float4 k1 = *(const float4*)(kb + 32);
        float d = qr[0] * k0.x + qr[1] * k0.y + qr[2] * k0.z + qr[3] * k0.w +
                  qr[4] * k1.x + qr[5] * k1.y + qr[6] * k1.z + qr[7] * k1.w;
        if (dy >= -1 && dy <= 1 && dx >= -1 && dx <= 1) {   // compile-time
            if ((unsigned)(gy + dy) < 56u && (unsigned)(gx + dx) < 56u) {
                const int t = (dy + 1) * 3 + (dx + 1);
                const float* wk = wf + (1 * 9 + t) * 64 + sb;
                float4 w0 = *(const float4*)(wk);
                float4 w1v = *(const float4*)(wk + 32);
                ocv[0] += w0.x * k0.x; ocv[1] += w0.y * k0.y;
                ocv[2] += w0.z * k0.z; ocv[3] += w0.w * k0.w;
                ocv[4] += w1v.x * k1.x; ocv[5] += w1v.y * k1.y;
                ocv[6] += w1v.z * k1.z; ocv[7] += w1v.w * k1.w;
            }
        }
        d += __shfl_xor_sync(0xffffffffu, d, 1);
        d += __shfl_xor_sync(0xffffffffu, d, 2);
        d += __shfl_xor_sync(0xffffffffu, d, 4);
        if ((j & 7) == s) attp[j >> 3] = d;
    }

    // PE dots: a = q.wp[:,0], bq = q.wp[:,1]  (bp term cancels analytically)
    float a = 0.f, bq = 0.f;
#pragma unroll
    for (int i = 0; i < 2; ++i)
#pragma unroll
        for (int j = 0; j < 4; ++j) {
            int ch = i * 32 + s * 4 + j;
            float2 w = __ldg((const float2*)wp + ch);
            a += qr[i * 4 + j] * w.x;
            bq += qr[i * 4 + j] * w.y;
        }
#pragma unroll
    for (int st = 1; st < 8; st <<= 1) {
        a += __shfl_xor_sync(0xffffffffu, a, st);
        bq += __shfl_xor_sync(0xffffffffu, bq, st);
    }

    // phase 2: distributed softmax over owned taps (<=4 per lane)
    const float scaling = 0.125f;        // 64^-0.5
    const float lstep = 2.f / 55.f;
    float mx = -1e30f;
#pragma unroll
    for (int i = 0; i < 4; ++i) {
        int j = s + 8 * i;
        if (j < 25) {
            int dy = j / 5 - 2, dx = j % 5 - 2;
            int gyj = refl(gy + dy), gxj = refl(gx + dx);
            float t = scaling * (attp[i] + a * ((float)(gx - gxj) * lstep) +
                                 bq * ((float)(gy - gyj) * lstep));
            attp[i] = t;
            mx = fmaxf(mx, t);
        } else {
            attp[i] = -1e30f;
        }
    }
    mx = fmaxf(mx, __shfl_xor_sync(0xffffffffu, mx, 1));
    mx = fmaxf(mx, __shfl_xor_sync(0xffffffffu, mx, 2));
    mx = fmaxf(mx, __shfl_xor_sync(0xffffffffu, mx, 4));
    float ssum = 0.f;
#pragma unroll
    for (int i = 0; i < 4; ++i) {
        float e = __expf(attp[i] - mx);
        attp[i] = e;
        ssum += e;
    }
    ssum += __shfl_xor_sync(0xffffffffu, ssum, 1);
    ssum += __shfl_xor_sync(0xffffffffu, ssum, 2);
    ssum += __shfl_xor_sync(0xffffffffu, ssum, 4);
    float inv = 1.f / ssum;
#pragma unroll
    for (int i = 0; i < 4; ++i) attp[i] *= inv;

    // phase 3: attention output + fused v-conv on inner taps
    float oa[8];
#pragma unroll
    for (int d = 0; d < 8; ++d) oa[d] = 0.f;
#pragma unroll
    for (int j = 0; j < 25; ++j) {
        const int dy = j / 5 - 2, dx = j % 5 - 2;
        const float w = __shfl_sync(0xffffffffu, attp[j >> 3], j & 7, 8);
        const float* vb = vs + (chidx + dy * 12 + dx) * PSTR + sb;
        float4 v0 = *(const float4*)(vb);
        float4 v1 = *(const float4*)(vb + 32);
        oa[0] += w * v0.x; oa[1] += w * v0.y; oa[2] += w * v0.z; oa[3] += w * v0.w;
        oa[4] += w * v1.x; oa[5] += w * v1.y; oa[6] += w * v1.z; oa[7] += w * v1.w;
        if (dy >= -1 && dy <= 1 && dx >= -1 && dx <= 1) {   // compile-time
            if ((unsigned)(gy + dy) < 56u && (unsigned)(gx + dx) < 56u) {
                const int t = (dy + 1) * 3 + (dx + 1);
                const float* wv = wf + (2 * 9 + t) * 64 + sb;
                float4 w0 = *(const float4*)(wv);
                float4 w1v = *(const float4*)(wv + 32);
                ocv[0] += w0.x * v0.x; ocv[1] += w0.y * v0.y;
                ocv[2] += w0.z * v0.z; ocv[3] += w0.w * v0.w;
                ocv[4] += w1v.x * v1.x; ocv[5] += w1v.y * v1.y;
                ocv[6] += w1v.z * v1.z; ocv[7] += w1v.w * v1.w;
            }
        }
    }

    const float r1 = rate1[0];
    const float r2 = rate2[0];
#pragma unroll
    for (int i = 0; i < 2; ++i)
#pragma unroll
        for (int j = 0; j < 4; ++j) {
            int ch = i * 32 + s * 4 + j;
            float res = r1 * oa[i * 4 + j] +
                        r2 * (ocv[i * 4 + j] + __ldg(b_dep + ch));
            out[((size_t)(b * 64 + ch) * 56 + gy) * 56 + gx] = res;
        }
}

// ---------------- launch ----------------
extern "C" void kernel_launch(void* const* d_in, const int* in_sizes, int n_in,
                              void* d_out, int out_size) {
    const float* x    = (const float*)d_in[0];
    const float* w1   = (const float*)d_in[1];
    const float* b1   = (const float*)d_in[2];
    const float* w2   = (const float*)d_in[3];
    const float* b2   = (const float*)d_in[4];
    const float* w3   = (const float*)d_in[5];
    const float* b3   = (const float*)d_in[6];
    const float* wp   = (const float*)d_in[7];
    // d_in[8] = bp (cancels analytically)
    const float* w_fc = (const float*)d_in[9];
    const float* w_dep = (const float*)d_in[10];
    const float* b_dep = (const float*)d_in[11];
    const float* rate1 = (const float*)d_in[12];
    const float* rate2 = (const float*)d_in[13];
    float* out = (float*)d_out;

    const int qkv_smem = (4096 + 64 * WS_STRIDE + 192) * 4;
    const int att_smem = (3 * HALO * PSTR + 1728) * 4;
    cudaFuncSetAttribute(qkv_kernel, cudaFuncAttributeMaxDynamicSharedMemorySize, qkv_smem);
    cudaFuncSetAttribute(attn_kernel, cudaFuncAttributeMaxDynamicSharedMemorySize, att_smem);

    qkv_kernel<<<dim3(49, 8), 256, qkv_smem>>>(x, w1, b1, w2, b2, w3, b3, w_fc, w_dep);
    attn_kernel<<<dim3(7, 14, 8), 256, att_smem>>>(wp, b_dep, rate1, rate2, out);
}

// round 8
// speedup vs baseline: 1.3320x; 1.1562x over previous
#include <cuda_runtime.h>

#define HWSZ 3136          // 56*56
#define NPOS 25088         // B*H*W
#define WS_STRIDE 196      // padded weight-smem row stride (floats)
#define PSTR 80            // attn smem per-position stride (floats): 320B == 64B mod 128B
#define HALO 96            // 12 x 8 halo positions (8x4 tile)

// ---------------- scratch (no cudaMalloc allowed) ----------------
__device__ float g_qkv[(size_t)NPOS * 192];   // [pos][q(64)|k(64)|v(64)]
__device__ float g_wfold[1728];               // [3][9][64] folded conv weights

__device__ __forceinline__ int refl(int i) {
    return i < 0 ? -i : (i >= 56 ? 110 - i : i);
}
// packed f32x2 helpers (Blackwell; ptxas never emits these from C++)
__device__ __forceinline__ unsigned long long bc2(float x) {
    unsigned long long r;
    asm("mov.b64 %0,{%1,%1};" : "=l"(r) : "f"(x));
    return r;
}
__device__ __forceinline__ unsigned long long pk2(float lo, float hi) {
    unsigned long long r;
    asm("mov.b64 %0,{%1,%2};" : "=l"(r) : "f"(lo), "f"(hi));
    return r;
}
__device__ __forceinline__ void fma2(unsigned long long& d, unsigned long long a,
                                     unsigned long long b) {
    asm("fma.rn.f32x2 %0,%1,%2,%0;" : "+l"(d) : "l"(a), "l"(b));
}
__device__ __forceinline__ float2 up2(unsigned long long v) {
    float2 r;
    asm("mov.b64 {%0,%1},%2;" : "=f"(r.x), "=f"(r.y) : "l"(v));
    return r;
}

// ---------------- kernel 1: q,k,v 1x1 convs (GEMM, f32x2 packed) ----------------
__global__ __launch_bounds__(256, 3) void qkv_kernel(
    const float* __restrict__ x,
    const float* __restrict__ w1, const float* __restrict__ b1,
    const float* __restrict__ w2, const float* __restrict__ b2,
    const float* __restrict__ w3, const float* __restrict__ b3,
    const float* __restrict__ w_fc, const float* __restrict__ w_dep) {
    extern __shared__ float sm[];
    float* xs = sm;                          // [64 cin][64 pos]
    float* ws = sm + 4096;                   // [64 cin][WS_STRIDE] holding 192 oc
    float* bs = sm + 4096 + 64 * WS_STRIDE;  // [192]

    const int b = blockIdx.y;
    const int pos0 = blockIdx.x * 64;        // 49 tiles * 64 = 3136 exact
    const int tid = threadIdx.x;

    // block (0,0) also folds the depthwise-conv weights for the attn kernel:
    // g_wfold[c][t][d] = sum_m w_dep[d][m][t] * w_fc[m][c]
    if (blockIdx.x == 0 && blockIdx.y == 0) {
        for (int i = tid; i < 1728; i += 256) {
            int c = i / 576, r = i % 576, t = r >> 6, d = r & 63;
            float s = 0.f;
#pragma unroll
            for (int m = 0; m < 9; ++m)
                s += w_dep[(d * 9 + m) * 9 + t] * w_fc[m * 3 + c];
            g_wfold[i] = s;
        }
    }

    for (int i = tid; i < 4096; i += 256) {
        int cin = i >> 6, p = i & 63;
        xs[i] = x[((size_t)(b * 64 + cin)) * HWSZ + pos0 + p];
    }
    for (int i = tid; i < 4096; i += 256) {
        int oc = i >> 6, cin = i & 63;
        ws[cin * WS_STRIDE + oc] = w1[i];
        ws[cin * WS_STRIDE + 64 + oc] = w2[i];
        ws[cin * WS_STRIDE + 128 + oc] = w3[i];
    }
    if (tid < 192)
        bs[tid] = (tid < 64) ? b1[tid] : (tid < 128 ? b2[tid - 64] : b3[tid - 128]);
    __syncthreads();

    const int w = tid >> 5;    // warp 0..7 -> 8 positions
    const int og = tid & 31;   // lane -> 6 output chans

    unsigned long long acc[8][3];
#pragma unroll
    for (int p = 0; p < 8; ++p)
#pragma unroll
        for (int q = 0; q < 3; ++q) acc[p][q] = 0ull;

    const float4* xs4 = (const float4*)xs;
#pragma unroll 2
    for (int cin = 0; cin < 64; ++cin) {
        float4 xa = xs4[cin * 16 + w * 2];       // positions 8w..8w+3 (broadcast)
        float4 xb = xs4[cin * 16 + w * 2 + 1];   // positions 8w+4..8w+7
        const float2* wr = (const float2*)(ws + cin * WS_STRIDE + og * 6);
        float2 wa = wr[0], wb = wr[1], wcv = wr[2];
        unsigned long long wq0 = pk2(wa.x, wa.y);
        unsigned long long wq1 = pk2(wb.x, wb.y);
        unsigned long long wq2 = pk2(wcv.x, wcv.y);
        unsigned long long xp[8] = {bc2(xa.x), bc2(xa.y), bc2(xa.z), bc2(xa.w),
                                    bc2(xb.x), bc2(xb.y), bc2(xb.z), bc2(xb.w)};
#pragma unroll
        for (int p = 0; p < 8; ++p) {
            fma2(acc[p][0], xp[p], wq0);
            fma2(acc[p][1], xp[p], wq1);
            fma2(acc[p][2], xp[p], wq2);
        }
    }

    float bl[6];
#pragma unroll
    for (int j = 0; j < 6; ++j) bl[j] = bs[og * 6 + j];

#pragma unroll
    for (int p = 0; p < 8; ++p) {
        float* dst = g_qkv + ((size_t)(b * HWSZ + pos0 + w * 8 + p)) * 192 + og * 6;
        float2 v0 = up2(acc[p][0]);
        float2 v1 = up2(acc[p][1]);
        float2 v2 = up2(acc[p][2]);
        float2 o0 = {v0.x + bl[0], v0.y + bl[1]};
        float2 o1 = {v1.x + bl[2], v1.y + bl[3]};
        float2 o2 = {v2.x + bl[4], v2.y + bl[5]};
        *(float2*)(dst + 0) = o0;
        *(float2*)(dst + 2) = o1;
        *(float2*)(dst + 4) = o2;
    }
}

// ---------------- kernel 2: fused attention + conv branch ----------------
// grid (7,14,8): 8x4 spatial tile, 256 threads: 8 subs/pos x 8 ch each.
// k,v staged in smem; q read straight from gmem (L1-resident working set).
// Distributed-tap softmax: lane s owns taps j%8==s.
__global__ __launch_bounds__(256, 3) void attn_kernel(
    const float* __restrict__ wp,
    const float* __restrict__ b_dep,
    const float* __restrict__ rate1,
    const float* __restrict__ rate2,
    float* __restrict__ out) {
    extern __shared__ float sm[];
    float* ks = sm;                      // [HALO][PSTR]
    float* vs = sm + HALO * PSTR;
    float* wf = sm + 2 * HALO * PSTR;    // [3][9][64] folded conv weights

    const int b = blockIdx.z;
    const int ty0 = blockIdx.y * 4;
    const int tx0 = blockIdx.x * 8;
    const int tid = threadIdx.x;

    for (int i = tid; i < 1728; i += 256) wf[i] = g_wfold[i];

    // halo load: 96 positions x k,v 128 channels, reflect-padded, f4 coalesced
    for (int i = tid; i < HALO * 32; i += 256) {
        int hpos = i >> 5;
        int c4 = 16 + (i & 31);
        int hy = hpos / 12, hx = hpos % 12;
        int gy = refl(ty0 + hy - 2);
        int gx = refl(tx0 + hx - 2);
        float4 v = *(const float4*)(g_qkv +
            ((size_t)(b * HWSZ + gy * 56 + gx)) * 192 + c4 * 4);
        float* arr = (c4 < 32) ? ks : vs;
        *(float4*)(arr + hpos * PSTR + (c4 & 15) * 4) = v;
    }
    __syncthreads();

    const int pos = tid >> 3;           // 0..31
    const int s = tid & 7;              // channel sub / tap owner
    const int ty = pos >> 3, tx = pos & 7;
    const int gy = ty0 + ty, gx = tx0 + tx;
    const int chidx = (ty + 2) * 12 + (tx + 2);
    const int sb = s * 4;

    // q from gmem. qr[i*4+j] = channel i*32 + s*4 + j
    const float* qg = g_qkv + ((size_t)(b * HWSZ + gy * 56 + gx)) * 192 + sb;
    float qr[8];
    {
        float4 v0 = *(const float4*)(qg);
        float4 v1 = *(const float4*)(qg + 32);
        qr[0] = v0.x; qr[1] = v0.y; qr[2] = v0.z; qr[3] = v0.w;
        qr[4] = v1.x; qr[5] = v1.y; qr[6] = v1.z; qr[7] = v1.w;
    }

    float ocv[8];
#pragma unroll
    for (int d = 0; d < 8; ++d) ocv[d] = 0.f;

    // q part of conv branch (9 taps, zero padding) — from gmem, no reflect
#pragma unroll
    for (int t = 0; t < 9; ++t) {
        const int dy = t / 3 - 1, dx = t % 3 - 1;
        if ((unsigned)(gy + dy) < 56u && (unsigned)(gx + dx) < 56u) {
            const float* qp = qg + (dy * 56 + dx) * 192;
            const float* wq = wf + (0 * 9 + t) * 64 + sb;
            float4 qv0 = *(const float4*)(qp), qv1 = *(const float4*)(qp + 32);
            float4 wv0 = *(const float4*)(wq), wv1 = *(const float4*)(wq + 32);
            ocv[0] += wv0.x * qv0.x; ocv[1] += wv0.y * qv0.y;
            ocv[2] += wv0.z * qv0.z; ocv[3] += wv0.w * qv0.w;
            ocv[4] += wv1.x * qv1.x; ocv[5] += wv1.y * qv1.y;
            ocv[6] += wv1.z * qv1.z; ocv[7] += wv1.w * qv1.w;
        }
    }

    // phase 1: 25 window dots, reduced immediately; lane s keeps taps j%8==s.
    float attp[4] = {0.f, 0.f, 0.f, 0.f};
#pragma unroll
    for (int j = 0; j < 25; ++j) {
        const int dy = j / 5 - 2, dx = j % 5 - 2;
        const float* kb = ks + (chidx + dy * 12 + dx) * PSTR + sb;
        float4 k0 = *(const float4*)(kb);
        float4 k1 = *(const float4*)(kb + 32);
        float d = qr[0] * k0.x + qr[1] * k0.y + qr[2] * k0.z + qr[3] * k0.w +
                  qr[4] * k1.x + qr[5] * k1.y + qr[6] * k1.z + qr[7] * k1.w;
        if (dy >= -1 && dy <= 1 && dx >= -1 && dx <= 1) {   // compile-time
            if ((unsigned)(gy + dy) < 56u && (unsigned)(gx + dx) < 56u) {
                const int t = (dy + 1) * 3 + (dx + 1);
                const float* wk = wf + (1 * 9 + t) * 64 + sb;
                float4 w0 = *(const float4*)(wk);
                float4 w1v = *(const float4*)(wk + 32);
                ocv[0] += w0.x * k0.x; ocv[1] += w0.y * k0.y;
                ocv[2] += w0.z * k0.z; ocv[3] += w0.w * k0.w;
                ocv[4] += w1v.x * k1.x; ocv[5] += w1v.y * k1.y;
                ocv[6] += w1v.z * k1.z; ocv[7] += w1v.w * k1.w;
            }
        }
        d += __shfl_xor_sync(0xffffffffu, d, 1);
        d += __shfl_xor_sync(0xffffffffu, d, 2);
        d += __shfl_xor_sync(0xffffffffu, d, 4);
        if ((j & 7) == s) attp[j >> 3] = d;
    }

    // PE dots: a = q.wp[:,0], bq = q.wp[:,1]  (bp term cancels analytically)
    float a = 0.f, bq = 0.f;
#pragma unroll
    for (int i = 0; i < 2; ++i)
#pragma unroll
        for (int j = 0; j < 4; ++j) {
            int ch = i * 32 + s * 4 + j;
            float2 w = __ldg((const float2*)wp + ch);
            a += qr[i * 4 + j] * w.x;
            bq += qr[i * 4 + j] * w.y;
        }
#pragma unroll
    for (int st = 1; st < 8; st <<= 1) {
        a += __shfl_xor_sync(0xffffffffu, a, st);
        bq += __shfl_xor_sync(0xffffffffu, bq, st);
    }

    // phase 2: distributed softmax over owned taps (<=4 per lane)
    const float scaling = 0.125f;        // 64^-0.5
    const float lstep = 2.f / 55.f;
    float mx = -1e30f;
#pragma unroll
    for (int i = 0; i < 4; ++i) {
        int j = s + 8 * i;
        if (j < 25) {
            int dy = j / 5 - 2, dx = j % 5 - 2;
            int gyj = refl(gy + dy), gxj = refl(gx + dx);
            float t = scaling * (attp[i] + a * ((float)(gx - gxj) * lstep) +
                                 bq * ((float)(gy - gyj) * lstep));
            attp[i] = t;
            mx = fmaxf(mx, t);
        } else {
            attp[i] = -1e30f;
        }
    }
    mx = fmaxf(mx, __shfl_xor_sync(0xffffffffu, mx, 1));
    mx = fmaxf(mx, __shfl_xor_sync(0xffffffffu, mx, 2));
    mx = fmaxf(mx, __shfl_xor_sync(0xffffffffu, mx, 4));
    float ssum = 0.f;
#pragma unroll
    for (int i = 0; i < 4; ++i) {
        float e = __expf(attp[i] - mx);
        attp[i] = e;
        ssum += e;
    }
    ssum += __shfl_xor_sync(0xffffffffu, ssum, 1);
    ssum += __shfl_xor_sync(0xffffffffu, ssum, 2);
    ssum += __shfl_xor_sync(0xffffffffu, ssum, 4);
    float inv = 1.f / ssum;
#pragma unroll
    for (int i = 0; i < 4; ++i) attp[i] *= inv;

    // phase 3: attention output + fused v-conv on inner taps
    float oa[8];
#pragma unroll
    for (int d = 0; d < 8; ++d) oa[d] = 0.f;
#pragma unroll
    for (int j = 0; j < 25; ++j) {
        const int dy = j / 5 - 2, dx = j % 5 - 2;
        const float w = __shfl_sync(0xffffffffu, attp[j >> 3], j & 7, 8);
        const float* vb = vs + (chidx + dy * 12 + dx) * PSTR + sb;
        float4 v0 = *(const float4*)(vb);
        float4 v1 = *(const float4*)(vb + 32);
        oa[0] += w * v0.x; oa[1] += w * v0.y; oa[2] += w * v0.z; oa[3] += w * v0.w;
        oa[4] += w * v1.x; oa[5] += w * v1.y; oa[6] += w * v1.z; oa[7] += w * v1.w;
        if (dy >= -1 && dy <= 1 && dx >= -1 && dx <= 1) {   // compile-time
            if ((unsigned)(gy + dy) < 56u && (unsigned)(gx + dx) < 56u) {
                const int t = (dy + 1) * 3 + (dx + 1);
                const float* wv = wf + (2 * 9 + t) * 64 + sb;
                float4 w0 = *(const float4*)(wv);
                float4 w1v = *(const float4*)(wv + 32);
                ocv[0] += w0.x * v0.x; ocv[1] += w0.y * v0.y;
                ocv[2] += w0.z * v0.z; ocv[3] += w0.w * v0.w;
                ocv[4] += w1v.x * v1.x; ocv[5] += w1v.y * v1.y;
                ocv[6] += w1v.z * v1.z; ocv[7] += w1v.w * v1.w;
            }
        }
    }

    const float r1 = rate1[0];
    const float r2 = rate2[0];
#pragma unroll
    for (int i = 0; i < 2; ++i)
#pragma unroll
        for (int j = 0; j < 4; ++j) {
            int ch = i * 32 + s * 4 + j;
            float res = r1 * oa[i * 4 + j] +
                        r2 * (ocv[i * 4 + j] + __ldg(b_dep + ch));
            out[((size_t)(b * 64 + ch) * 56 + gy) * 56 + gx] = res;
        }
}

// ---------------- launch ----------------
extern "C" void kernel_launch(void* const* d_in, const int* in_sizes, int n_in,
                              void* d_out, int out_size) {
    const float* x    = (const float*)d_in[0];
    const float* w1   = (const float*)d_in[1];
    const float* b1   = (const float*)d_in[2];
    const float* w2   = (const float*)d_in[3];
    const float* b2   = (const float*)d_in[4];
    const float* w3   = (const float*)d_in[5];
    const float* b3   = (const float*)d_in[6];
    const float* wp   = (const float*)d_in[7];
    // d_in[8] = bp (cancels analytically)
    const float* w_fc = (const float*)d_in[9];
    const float* w_dep = (const float*)d_in[10];
    const float* b_dep = (const float*)d_in[11];
    const float* rate1 = (const float*)d_in[12];
    const float* rate2 = (const float*)d_in[13];
    float* out = (float*)d_out;

    const int qkv_smem = (4096 + 64 * WS_STRIDE + 192) * 4;
    const int att_smem = (2 * HALO * PSTR + 1728) * 4;
    cudaFuncSetAttribute(qkv_kernel, cudaFuncAttributeMaxDynamicSharedMemorySize, qkv_smem);
    cudaFuncSetAttribute(attn_kernel, cudaFuncAttributeMaxDynamicSharedMemorySize, att_smem);

    qkv_kernel<<<dim3(49, 8), 256, qkv_smem>>>(x, w1, b1, w2, b2, w3, b3, w_fc, w_dep);
    attn_kernel<<<dim3(7, 14, 8), 256, att_smem>>>(wp, b_dep, rate1, rate2, out);
}

// round 9
// speedup vs baseline: 1.3360x; 1.0030x over previous
#include <cuda_runtime.h>

#define HWSZ 3136          // 56*56
#define NPOS 25088         // B*H*W
#define WS_STRIDE 196      // padded weight-smem row stride (floats)
#define PSTR 64            // attn smem per-position stride: 8-lane LDS.128 phases are conflict-free at any 16B-aligned stride
#define HALO 96            // 12 x 8 halo positions (8x4 tile)

// ---------------- scratch (no cudaMalloc allowed) ----------------
__device__ float g_qkv[(size_t)NPOS * 192];   // [pos][q(64)|k(64)|v(64)]
__device__ float g_wfold[1728];               // [3][9][64] folded conv weights

__device__ __forceinline__ int refl(int i) {
    return i < 0 ? -i : (i >= 56 ? 110 - i : i);
}
// packed f32x2 helpers (Blackwell; ptxas never emits these from C++)
__device__ __forceinline__ unsigned long long bc2(float x) {
    unsigned long long r;
    asm("mov.b64 %0,{%1,%1};" : "=l"(r) : "f"(x));
    return r;
}
__device__ __forceinline__ unsigned long long pk2(float lo, float hi) {
    unsigned long long r;
    asm("mov.b64 %0,{%1,%2};" : "=l"(r) : "f"(lo), "f"(hi));
    return r;
}
__device__ __forceinline__ void fma2(unsigned long long& d, unsigned long long a,
                                     unsigned long long b) {
    asm("fma.rn.f32x2 %0,%1,%2,%0;" : "+l"(d) : "l"(a), "l"(b));
}
__device__ __forceinline__ float2 up2(unsigned long long v) {
    float2 r;
    asm("mov.b64 {%0,%1},%2;" : "=f"(r.x), "=f"(r.y) : "l"(v));
    return r;
}

// ---------------- kernel 1: q,k,v 1x1 convs (GEMM, f32x2 packed) ----------------
__global__ __launch_bounds__(256, 3) void qkv_kernel(
    const float* __restrict__ x,
    const float* __restrict__ w1, const float* __restrict__ b1,
    const float* __restrict__ w2, const float* __restrict__ b2,
    const float* __restrict__ w3, const float* __restrict__ b3,
    const float* __restrict__ w_fc, const float* __restrict__ w_dep) {
    extern __shared__ float sm[];
    float* xs = sm;                          // [64 cin][64 pos]
    float* ws = sm + 4096;                   // [64 cin][WS_STRIDE] holding 192 oc
    float* bs = sm + 4096 + 64 * WS_STRIDE;  // [192]

    const int b = blockIdx.y;
    const int pos0 = blockIdx.x * 64;        // 49 tiles * 64 = 3136 exact
    const int tid = threadIdx.x;

    // block (0,0) also folds the depthwise-conv weights for the attn kernel:
    // g_wfold[c][t][d] = sum_m w_dep[d][m][t] * w_fc[m][c]
    if (blockIdx.x == 0 && blockIdx.y == 0) {
        for (int i = tid; i < 1728; i += 256) {
            int c = i / 576, r = i % 576, t = r >> 6, d = r & 63;
            float s = 0.f;
#pragma unroll
            for (int m = 0; m < 9; ++m)
                s += w_dep[(d * 9 + m) * 9 + t] * w_fc[m * 3 + c];
            g_wfold[i] = s;
        }
    }

    for (int i = tid; i < 4096; i += 256) {
        int cin = i >> 6, p = i & 63;
        xs[i] = x[((size_t)(b * 64 + cin)) * HWSZ + pos0 + p];
    }
    for (int i = tid; i < 4096; i += 256) {
        int oc = i >> 6, cin = i & 63;
        ws[cin * WS_STRIDE + oc] = w1[i];
        ws[cin * WS_STRIDE + 64 + oc] = w2[i];
        ws[cin * WS_STRIDE + 128 + oc] = w3[i];
    }
    if (tid < 192)
        bs[tid] = (tid < 64) ? b1[tid] : (tid < 128 ? b2[tid - 64] : b3[tid - 128]);
    __syncthreads();

    const int w = tid >> 5;    // warp 0..7 -> 8 positions
    const int og = tid & 31;   // lane -> 6 output chans

    unsigned long long acc[8][3];
#pragma unroll
    for (int p = 0; p < 8; ++p)
#pragma unroll
        for (int q = 0; q < 3; ++q) acc[p][q] = 0ull;

    const float4* xs4 = (const float4*)xs;
#pragma unroll 2
    for (int cin = 0; cin < 64; ++cin) {
        float4 xa = xs4[cin * 16 + w * 2];       // positions 8w..8w+3 (broadcast)
        float4 xb = xs4[cin * 16 + w * 2 + 1];   // positions 8w+4..8w+7
        const float2* wr = (const float2*)(ws + cin * WS_STRIDE + og * 6);
        float2 wa = wr[0], wb = wr[1], wcv = wr[2];
        unsigned long long wq0 = pk2(wa.x, wa.y);
        unsigned long long wq1 = pk2(wb.x, wb.y);
        unsigned long long wq2 = pk2(wcv.x, wcv.y);
        unsigned long long xp[8] = {bc2(xa.x), bc2(xa.y), bc2(xa.z), bc2(xa.w),
                                    bc2(xb.x), bc2(xb.y), bc2(xb.z), bc2(xb.w)};
#pragma unroll
        for (int p = 0; p < 8; ++p) {
            fma2(acc[p][0], xp[p], wq0);
            fma2(acc[p][1], xp[p], wq1);
            fma2(acc[p][2], xp[p], wq2);
        }
    }

    float bl[6];
#pragma unroll
    for (int j = 0; j < 6; ++j) bl[j] = bs[og * 6 + j];

#pragma unroll
    for (int p = 0; p < 8; ++p) {
        float* dst = g_qkv + ((size_t)(b * HWSZ + pos0 + w * 8 + p)) * 192 + og * 6;
        float2 v0 = up2(acc[p][0]);
        float2 v1 = up2(acc[p][1]);
        float2 v2 = up2(acc[p][2]);
        float2 o0 = {v0.x + bl[0], v0.y + bl[1]};
        float2 o1 = {v1.x + bl[2], v1.y + bl[3]};
        float2 o2 = {v2.x + bl[4], v2.y + bl[5]};
        *(float2*)(dst + 0) = o0;
        *(float2*)(dst + 2) = o1;
        *(float2*)(dst + 4) = o2;
    }
}

// ---------------- kernel 2: fused attention + conv branch ----------------
// grid (7,14,8): 8x4 spatial tile, 256 threads: 8 subs/pos x 8 ch each.
// k,v staged in smem (PSTR=64); q read from gmem (L1-resident).
// Distributed-tap softmax; phase-3 uses one merged accumulator.
__global__ __launch_bounds__(256, 4) void attn_kernel(
    const float* __restrict__ wp,
    const float* __restrict__ b_dep,
    const float* __restrict__ rate1,
    const float* __restrict__ rate2,
    float* __restrict__ out) {
    extern __shared__ float sm[];
    float* ks = sm;                      // [HALO][PSTR]
    float* vs = sm + HALO * PSTR;
    float* wf = sm + 2 * HALO * PSTR;    // [3][9][64] folded conv weights

    const int b = blockIdx.z;
    const int ty0 = blockIdx.y * 4;
    const int tx0 = blockIdx.x * 8;
    const int tid = threadIdx.x;

    for (int i = tid; i < 1728; i += 256) wf[i] = g_wfold[i];

    // halo load: 96 positions x k,v 128 channels, reflect-padded, f4 coalesced
    for (int i = tid; i < HALO * 32; i += 256) {
        int hpos = i >> 5;
        int c4 = 16 + (i & 31);
        int hy = hpos / 12, hx = hpos % 12;
        int gy = refl(ty0 + hy - 2);
        int gx = refl(tx0 + hx - 2);
        float4 v = *(const float4*)(g_qkv +
            ((size_t)(b * HWSZ + gy * 56 + gx)) * 192 + c4 * 4);
        float* arr = (c4 < 32) ? ks : vs;
        *(float4*)(arr + hpos * PSTR + (c4 & 15) * 4) = v;
    }
    __syncthreads();

    const int pos = tid >> 3;           // 0..31
    const int s = tid & 7;              // channel sub / tap owner
    const int ty = pos >> 3, tx = pos & 7;
    const int gy = ty0 + ty, gx = tx0 + tx;
    const int chidx = (ty + 2) * 12 + (tx + 2);
    const int sb = s * 4;

    // q from gmem. qr[i*4+j] = channel i*32 + s*4 + j
    const float* qg = g_qkv + ((size_t)(b * HWSZ + gy * 56 + gx)) * 192 + sb;
    float qr[8];
    {
        float4 v0 = *(const float4*)(qg);
        float4 v1 = *(const float4*)(qg + 32);
        qr[0] = v0.x; qr[1] = v0.y; qr[2] = v0.z; qr[3] = v0.w;
        qr[4] = v1.x; qr[5] = v1.y; qr[6] = v1.z; qr[7] = v1.w;
    }

    float ocv[8];
#pragma unroll
    for (int d = 0; d < 8; ++d) ocv[d] = 0.f;

    // q part of conv branch (9 taps, zero padding) — from gmem, no reflect
#pragma unroll
    for (int t = 0; t < 9; ++t) {
        const int dy = t / 3 - 1, dx = t % 3 - 1;
        if ((unsigned)(gy + dy) < 56u && (unsigned)(gx + dx) < 56u) {
            const float* qp = qg + (dy * 56 + dx) * 192;
            const float* wq = wf + (0 * 9 + t) * 64 + sb;
            float4 qv0 = *(const float4*)(qp), qv1 = *(const float4*)(qp + 32);
            float4 wv0 = *(const float4*)(wq), wv1 = *(const float4*)(wq + 32);
            ocv[0] += wv0.x * qv0.x; ocv[1] += wv0.y * qv0.y;
            ocv[2] += wv0.z * qv0.z; ocv[3] += wv0.w * qv0.w;
            ocv[4] += wv1.x * qv1.x; ocv[5] += wv1.y * qv1.y;
            ocv[6] += wv1.z * qv1.z; ocv[7] += wv1.w * qv1.w;
        }
    }

    // phase 1: 25 window dots, reduced immediately; lane s keeps taps j%8==s.
    float attp[4] = {0.f, 0.f, 0.f, 0.f};
#pragma unroll
    for (int j = 0; j < 25; ++j) {
        const int dy = j / 5 - 2, dx = j % 5 - 2;
        const float* kb = ks + (chidx + dy * 12 + dx) * PSTR + sb;
        float4 k0 = *(const float4*)(kb);
        float4 k1 = *(const float4*)(kb + 32);
        float d = qr[0] * k0.x + qr[1] * k0.y + qr[2] * k0.z + qr[3] * k0.w +
                  qr[4] * k1.x + qr[5] * k1.y + qr[6] * k1.z + qr[7] * k1.w;
        if (dy >= -1 && dy <= 1 && dx >= -1 && dx <= 1) {   // compile-time
            if ((unsigned)(gy + dy) < 56u && (unsigned)(gx + dx) < 56u) {
                const int t = (dy + 1) * 3 + (dx + 1);
                const float* wk = wf + (1 * 9 + t) * 64 + sb;
                float4 w0 = *(const float4*)(wk);
                float4 w1v = *(const float4*)(wk + 32);
                ocv[0] += w0.x * k0.x; ocv[1] += w0.y * k0.y;
                ocv[2] += w0.z * k0.z; ocv[3] += w0.w * k0.w;
                ocv[4] += w1v.x * k1.x; ocv[5] += w1v.y * k1.y;
                ocv[6] += w1v.z * k1.z; ocv[7] += w1v.w * k1.w;
            }
        }
        d += __shfl_xor_sync(0xffffffffu, d, 1);
        d += __shfl_xor_sync(0xffffffffu, d, 2);
        d += __shfl_xor_sync(0xffffffffu, d, 4);
        if ((j & 7) == s) attp[j >> 3] = d;
    }

    // PE dots: a = q.wp[:,0], bq = q.wp[:,1]  (bp term cancels analytically)
    float a = 0.f, bq = 0.f;
#pragma unroll
    for (int i = 0; i < 2; ++i)
#pragma unroll
        for (int j = 0; j < 4; ++j) {
            int ch = i * 32 + s * 4 + j;
            float2 w = __ldg((const float2*)wp + ch);
            a += qr[i * 4 + j] * w.x;
            bq += qr[i * 4 + j] * w.y;
        }
#pragma unroll
    for (int st = 1; st < 8; st <<= 1) {
        a += __shfl_xor_sync(0xffffffffu, a, st);
        bq += __shfl_xor_sync(0xffffffffu, bq, st);
    }

    // phase 2: distributed softmax over owned taps (<=4 per lane)
    const float scaling = 0.125f;        // 64^-0.5
    const float lstep = 2.f / 55.f;
    float mx = -1e30f;
#pragma unroll
    for (int i = 0; i < 4; ++i) {
        int j = s + 8 * i;
        if (j < 25) {
            int dy = j / 5 - 2, dx = j % 5 - 2;
            int gyj = refl(gy + dy), gxj = refl(gx + dx);
            float t = scaling * (attp[i] + a * ((float)(gx - gxj) * lstep) +
                                 bq * ((float)(gy - gyj) * lstep));
            attp[i] = t;
            mx = fmaxf(mx, t);
        } else {
            attp[i] = -1e30f;
        }
    }
    mx = fmaxf(mx, __shfl_xor_sync(0xffffffffu, mx, 1));
    mx = fmaxf(mx, __shfl_xor_sync(0xffffffffu, mx, 2));
    mx = fmaxf(mx, __shfl_xor_sync(0xffffffffu, mx, 4));
    float ssum = 0.f;
#pragma unroll
    for (int i = 0; i < 4; ++i) {
        float e = __expf(attp[i] - mx);
        attp[i] = e;
        ssum += e;
    }
    ssum += __shfl_xor_sync(0xffffffffu, ssum, 1);
    ssum += __shfl_xor_sync(0xffffffffu, ssum, 2);
    ssum += __shfl_xor_sync(0xffffffffu, ssum, 4);

    const float r1 = rate1[0];
    const float r2 = rate2[0];
    // fold r1 and the softmax normalization into the attention coefficients
    float invr1 = r1 / ssum;
#pragma unroll
    for (int i = 0; i < 4; ++i) attp[i] *= invr1;

    // phase 3: merged accumulator: res_v = sum_j (r1*att_j + r2*wv_t)*v_j
    float oav[8];
#pragma unroll
    for (int d = 0; d < 8; ++d) oav[d] = 0.f;
#pragma unroll
    for (int j = 0; j < 25; ++j) {
        const int dy = j / 5 - 2, dx = j % 5 - 2;
        float c0x, c0y, c0z, c0w, c1x, c1y, c1z, c1w;
        const float w = __shfl_sync(0xffffffffu, attp[j >> 3], j & 7, 8);
        c0x = c0y = c0z = c0w = c1x = c1y = c1z = c1w = w;
        if (dy >= -1 && dy <= 1 && dx >= -1 && dx <= 1) {   // compile-time
            if ((unsigned)(gy + dy) < 56u && (unsigned)(gx + dx) < 56u) {
                const int t = (dy + 1) * 3 + (dx + 1);
                const float* wv = wf + (2 * 9 + t) * 64 + sb;
                float4 w0 = *(const float4*)(wv);
                float4 w1v = *(const float4*)(wv + 32);
                c0x += r2 * w0.x; c0y += r2 * w0.y; c0z += r2 * w0.z; c0w += r2 * w0.w;
                c1x += r2 * w1v.x; c1y += r2 * w1v.y; c1z += r2 * w1v.z; c1w += r2 * w1v.w;
            }
        }
        const float* vb = vs + (chidx + dy * 12 + dx) * PSTR + sb;
        float4 v0 = *(const float4*)(vb);
        float4 v1 = *(const float4*)(vb + 32);
        oav[0] += c0x * v0.x; oav[1] += c0y * v0.y;
        oav[2] += c0z * v0.z; oav[3] += c0w * v0.w;
        oav[4] += c1x * v1.x; oav[5] += c1y * v1.y;
        oav[6] += c1z * v1.z; oav[7] += c1w * v1.w;
    }

#pragma unroll
    for (int i = 0; i < 2; ++i)
#pragma unroll
        for (int j = 0; j < 4; ++j) {
            int ch = i * 32 + s * 4 + j;
            float res = oav[i * 4 + j] +
                        r2 * (ocv[i * 4 + j] + __ldg(b_dep + ch));
            out[((size_t)(b * 64 + ch) * 56 + gy) * 56 + gx] = res;
        }
}

// ---------------- launch ----------------
extern "C" void kernel_launch(void* const* d_in, const int* in_sizes, int n_in,
                              void* d_out, int out_size) {
    const float* x    = (const float*)d_in[0];
    const float* w1   = (const float*)d_in[1];
    const float* b1   = (const float*)d_in[2];
    const float* w2   = (const float*)d_in[3];
    const float* b2   = (const float*)d_in[4];
    const float* w3   = (const float*)d_in[5];
    const float* b3   = (const float*)d_in[6];
    const float* wp   = (const float*)d_in[7];
    // d_in[8] = bp (cancels analytically)
    const float* w_fc = (const float*)d_in[9];
    const float* w_dep = (const float*)d_in[10];
    const float* b_dep = (const float*)d_in[11];
    const float* rate1 = (const float*)d_in[12];
    const float* rate2 = (const float*)d_in[13];
    float* out = (float*)d_out;

    const int qkv_smem = (4096 + 64 * WS_STRIDE + 192) * 4;
    const int att_smem = (2 * HALO * PSTR + 1728) * 4;
    cudaFuncSetAttribute(qkv_kernel, cudaFuncAttributeMaxDynamicSharedMemorySize, qkv_smem);
    cudaFuncSetAttribute(attn_kernel, cudaFuncAttributeMaxDynamicSharedMemorySize, att_smem);

    qkv_kernel<<<dim3(49, 8), 256, qkv_smem>>>(x, w1, b1, w2, b2, w3, b3, w_fc, w_dep);
    attn_kernel<<<dim3(7, 14, 8), 256, att_smem>>>(wp, b_dep, rate1, rate2, out);
}

// round 10
// speedup vs baseline: 1.4774x; 1.1058x over previous
#include <cuda_runtime.h>

#define HWSZ 3136          // 56*56
#define NPOS 25088         // B*H*W
#define WS_STRIDE 196      // qkv padded weight-smem row stride (floats)
#define PSTR 64            // attn smem per-position stride (floats)
#define HALOW 12           // 12x12 halo for 8x8 tile
#define HALON 144

// ---------------- scratch (no cudaMalloc allowed) ----------------
__device__ float g_qkv[(size_t)NPOS * 192];   // [pos][q(64)|k(64)|v(64)]
__device__ float g_wfold[1728];               // [3][9][64] folded conv weights

__device__ __forceinline__ int refl(int i) {
    return i < 0 ? -i : (i >= 56 ? 110 - i : i);
}
// packed f32x2 helpers (Blackwell; ptxas never emits these from C++)
__device__ __forceinline__ unsigned long long bc2(float x) {
    unsigned long long r;
    asm("mov.b64 %0,{%1,%1};" : "=l"(r) : "f"(x));
    return r;
}
__device__ __forceinline__ unsigned long long pk2(float lo, float hi) {
    unsigned long long r;
    asm("mov.b64 %0,{%1,%2};" : "=l"(r) : "f"(lo), "f"(hi));
    return r;
}
__device__ __forceinline__ void fma2(unsigned long long& d, unsigned long long a,
                                     unsigned long long b) {
    asm("fma.rn.f32x2 %0,%1,%2,%0;" : "+l"(d) : "l"(a), "l"(b));
}
__device__ __forceinline__ float2 up2(unsigned long long v) {
    float2 r;
    asm("mov.b64 {%0,%1},%2;" : "=f"(r.x), "=f"(r.y) : "l"(v));
    return r;
}

// ---------------- kernel 1: q,k,v 1x1 convs (GEMM, f32x2 packed) ----------------
__global__ __launch_bounds__(256, 3) void qkv_kernel(
    const float* __restrict__ x,
    const float* __restrict__ w1, const float* __restrict__ b1,
    const float* __restrict__ w2, const float* __restrict__ b2,
    const float* __restrict__ w3, const float* __restrict__ b3,
    const float* __restrict__ w_fc, const float* __restrict__ w_dep) {
    extern __shared__ float sm[];
    float* xs = sm;                          // [64 cin][64 pos]
    float* ws = sm + 4096;                   // [64 cin][WS_STRIDE] holding 192 oc
    float* bs = sm + 4096 + 64 * WS_STRIDE;  // [192]

    const int b = blockIdx.y;
    const int pos0 = blockIdx.x * 64;        // 49 tiles * 64 = 3136 exact
    const int tid = threadIdx.x;

    // block (0,0) also folds the depthwise-conv weights for the attn kernel:
    // g_wfold[c][t][d] = sum_m w_dep[d][m][t] * w_fc[m][c]
    if (blockIdx.x == 0 && blockIdx.y == 0) {
        for (int i = tid; i < 1728; i += 256) {
            int c = i / 576, r = i % 576, t = r >> 6, d = r & 63;
            float s = 0.f;
#pragma unroll
            for (int m = 0; m < 9; ++m)
                s += w_dep[(d * 9 + m) * 9 + t] * w_fc[m * 3 + c];
            g_wfold[i] = s;
        }
    }

    for (int i = tid; i < 4096; i += 256) {
        int cin = i >> 6, p = i & 63;
        xs[i] = x[((size_t)(b * 64 + cin)) * HWSZ + pos0 + p];
    }
    for (int i = tid; i < 4096; i += 256) {
        int oc = i >> 6, cin = i & 63;
        ws[cin * WS_STRIDE + oc] = w1[i];
        ws[cin * WS_STRIDE + 64 + oc] = w2[i];
        ws[cin * WS_STRIDE + 128 + oc] = w3[i];
    }
    if (tid < 192)
        bs[tid] = (tid < 64) ? b1[tid] : (tid < 128 ? b2[tid - 64] : b3[tid - 128]);
    __syncthreads();

    const int w = tid >> 5;    // warp 0..7 -> 8 positions
    const int og = tid & 31;   // lane -> 6 output chans

    unsigned long long acc[8][3];
#pragma unroll
    for (int p = 0; p < 8; ++p)
#pragma unroll
        for (int q = 0; q < 3; ++q) acc[p][q] = 0ull;

    const float4* xs4 = (const float4*)xs;
#pragma unroll 2
    for (int cin = 0; cin < 64; ++cin) {
        float4 xa = xs4[cin * 16 + w * 2];       // positions 8w..8w+3 (broadcast)
        float4 xb = xs4[cin * 16 + w * 2 + 1];   // positions 8w+4..8w+7
        const float2* wr = (const float2*)(ws + cin * WS_STRIDE + og * 6);
        float2 wa = wr[0], wb = wr[1], wcv = wr[2];
        unsigned long long wq0 = pk2(wa.x, wa.y);
        unsigned long long wq1 = pk2(wb.x, wb.y);
        unsigned long long wq2 = pk2(wcv.x, wcv.y);
        unsigned long long xp[8] = {bc2(xa.x), bc2(xa.y), bc2(xa.z), bc2(xa.w),
                                    bc2(xb.x), bc2(xb.y), bc2(xb.z), bc2(xb.w)};
#pragma unroll
        for (int p = 0; p < 8; ++p) {
            fma2(acc[p][0], xp[p], wq0);
            fma2(acc[p][1], xp[p], wq1);
            fma2(acc[p][2], xp[p], wq2);
        }
    }

    float bl[6];
#pragma unroll
    for (int j = 0; j < 6; ++j) bl[j] = bs[og * 6 + j];

#pragma unroll
    for (int p = 0; p < 8; ++p) {
        float* dst = g_qkv + ((size_t)(b * HWSZ + pos0 + w * 8 + p)) * 192 + og * 6;
        float2 v0 = up2(acc[p][0]);
        float2 v1 = up2(acc[p][1]);
        float2 v2 = up2(acc[p][2]);
        float2 o0 = {v0.x + bl[0], v0.y + bl[1]};
        float2 o1 = {v1.x + bl[2], v1.y + bl[3]};
        float2 o2 = {v2.x + bl[4], v2.y + bl[5]};
        *(float2*)(dst + 0) = o0;
        *(float2*)(dst + 2) = o1;
        *(float2*)(dst + 4) = o2;
    }
}

// ---------------- kernel 2: fused attention + conv branch ----------------
// grid (7,7,8): 8x8 tile, 256 threads: 8 subs x 32 horizontal position PAIRS.
// Each thread serves positions (gy,gx0) and (gy,gx0+1): the 5x5 tap windows
// overlap, so each k/v float4 pair is loaded ONCE for both (30 loads vs 50).
// wf weights read via __ldg (L1-hot). Distributed-tap softmax per position.
__global__ __launch_bounds__(256, 3) void attn_kernel(
    const float* __restrict__ wp,
    const float* __restrict__ b_dep,
    const float* __restrict__ rate1,
    const float* __restrict__ rate2,
    float* __restrict__ out) {
    extern __shared__ float sm[];
    float* ks = sm;                      // [HALON][PSTR]
    float* vs = sm + HALON * PSTR;

    const int b = blockIdx.z;
    const int ty0 = blockIdx.y * 8;
    const int tx0 = blockIdx.x * 8;
    const int tid = threadIdx.x;
    const float* wfold = g_wfold;

    // halo load: 144 positions x k,v 128 channels, reflect-padded, f4 coalesced
    for (int i = tid; i < HALON * 32; i += 256) {
        int hpos = i >> 5;
        int c4 = 16 + (i & 31);
        int hy = hpos / HALOW, hx = hpos % HALOW;
        int gy = refl(ty0 + hy - 2);
        int gx = refl(tx0 + hx - 2);
        float4 v = *(const float4*)(g_qkv +
            ((size_t)(b * HWSZ + gy * 56 + gx)) * 192 + c4 * 4);
        float* arr = (c4 < 32) ? ks : vs;
        *(float4*)(arr + hpos * PSTR + (c4 & 15) * 4) = v;
    }
    __syncthreads();

    const int pp = tid >> 3;            // pair 0..31
    const int s = tid & 7;              // channel sub / tap owner
    const int py = pp >> 2;             // 0..7
    const int px0 = (pp & 3) * 2;       // 0,2,4,6
    const int gy = ty0 + py, gx0 = tx0 + px0, gx1 = gx0 + 1;
    const int chidx = (py + 2) * HALOW + (px0 + 2);
    const int sb = s * 4;

    // q for both positions from gmem (L1-resident)
    const float* qg0 = g_qkv + ((size_t)(b * HWSZ + gy * 56 + gx0)) * 192 + sb;
    float qr0[8], qr1[8];
    {
        float4 v0 = *(const float4*)(qg0);
        float4 v1 = *(const float4*)(qg0 + 32);
        qr0[0] = v0.x; qr0[1] = v0.y; qr0[2] = v0.z; qr0[3] = v0.w;
        qr0[4] = v1.x; qr0[5] = v1.y; qr0[6] = v1.z; qr0[7] = v1.w;
        float4 u0 = *(const float4*)(qg0 + 192);
        float4 u1 = *(const float4*)(qg0 + 224);
        qr1[0] = u0.x; qr1[1] = u0.y; qr1[2] = u0.z; qr1[3] = u0.w;
        qr1[4] = u1.x; qr1[5] = u1.y; qr1[6] = u1.z; qr1[7] = u1.w;
    }

    float ocv0[8], ocv1[8];
#pragma unroll
    for (int d = 0; d < 8; ++d) { ocv0[d] = 0.f; ocv1[d] = 0.f; }

    // q-conv: 12 shared data loads serve 9+9 taps (zero padding via predicate)
#pragma unroll
    for (int dy = -1; dy <= 1; ++dy)
#pragma unroll
        for (int dx = -1; dx <= 2; ++dx) {
            if ((unsigned)(gy + dy) < 56u && (unsigned)(gx0 + dx) < 56u) {
                const float* qp = qg0 + (dy * 56 + dx) * 192;
                float4 q0 = *(const float4*)(qp);
                float4 q1 = *(const float4*)(qp + 32);
                if (dx <= 1) {
                    const float* wq = wfold + ((dy + 1) * 3 + dx + 1) * 64 + sb;
                    float4 w0 = __ldg((const float4*)(wq));
                    float4 w1 = __ldg((const float4*)(wq + 32));
                    ocv0[0] += w0.x * q0.x; ocv0[1] += w0.y * q0.y;
                    ocv0[2] += w0.z * q0.z; ocv0[3] += w0.w * q0.w;
                    ocv0[4] += w1.x * q1.x; ocv0[5] += w1.y * q1.y;
                    ocv0[6] += w1.z * q1.z; ocv0[7] += w1.w * q1.w;
                }
                if (dx >= 0) {
                    const float* wq = wfold + ((dy + 1) * 3 + dx) * 64 + sb;
                    float4 w0 = __ldg((const float4*)(wq));
                    float4 w1 = __ldg((const float4*)(wq + 32));
                    ocv1[0] += w0.x * q0.x; ocv1[1] += w0.y * q0.y;
                    ocv1[2] += w0.z * q0.z; ocv1[3] += w0.w * q0.w;
                    ocv1[4] += w1.x * q1.x; ocv1[5] += w1.y * q1.y;
                    ocv1[6] += w1.z * q1.z; ocv1[7] += w1.w * q1.w;
                }
            }
        }

    // phase 1: 30 k loads -> 50 dots (25 per position) + fused k-conv
    float attp0[4] = {0.f, 0.f, 0.f, 0.f};
    float attp1[4] = {0.f, 0.f, 0.f, 0.f};
#pragma unroll
    for (int dy = -2; dy <= 2; ++dy)
#pragma unroll
        for (int dx = -2; dx <= 3; ++dx) {
            const float* kb = ks + (chidx + dy * HALOW + dx) * PSTR + sb;
            float4 k0 = *(const float4*)(kb);
            float4 k1 = *(const float4*)(kb + 32);
            // fused k-conv (inner taps, zero padding)
            if (dy >= -1 && dy <= 1) {
                if ((unsigned)(gy + dy) < 56u && (unsigned)(gx0 + dx) < 56u) {
                    if (dx >= -1 && dx <= 1) {
                        const float* wk = wfold + 576 + ((dy + 1) * 3 + dx + 1) * 64 + sb;
                        float4 w0 = __ldg((const float4*)(wk));
                        float4 w1 = __ldg((const float4*)(wk + 32));
                        ocv0[0] += w0.x * k0.x; ocv0[1] += w0.y * k0.y;
                        ocv0[2] += w0.z * k0.z; ocv0[3] += w0.w * k0.w;
                        ocv0[4] += w1.x * k1.x; ocv0[5] += w1.y * k1.y;
                        ocv0[6] += w1.z * k1.z; ocv0[7] += w1.w * k1.w;
                    }
                    if (dx >= 0 && dx <= 2) {
                        const float* wk = wfold + 576 + ((dy + 1) * 3 + dx) * 64 + sb;
                        float4 w0 = __ldg((const float4*)(wk));
                        float4 w1 = __ldg((const float4*)(wk + 32));
                        ocv1[0] += w0.x * k0.x; ocv1[1] += w0.y * k0.y;
                        ocv1[2] += w0.z * k0.z; ocv1[3] += w0.w * k0.w;
                        ocv1[4] += w1.x * k1.x; ocv1[5] += w1.y * k1.y;
                        ocv1[6] += w1.z * k1.z; ocv1[7] += w1.w * k1.w;
                    }
                }
            }
            if (dx <= 2) {   // tap (dy,dx) of pos0
                float d = qr0[0] * k0.x + qr0[1] * k0.y + qr0[2] * k0.z + qr0[3] * k0.w +
                          qr0[4] * k1.x + qr0[5] * k1.y + qr0[6] * k1.z + qr0[7] * k1.w;
                d += __shfl_xor_sync(0xffffffffu, d, 1);
                d += __shfl_xor_sync(0xffffffffu, d, 2);
                d += __shfl_xor_sync(0xffffffffu, d, 4);
                const int j = (dy + 2) * 5 + dx + 2;
                if ((j & 7) == s) attp0[j >> 3] = d;
            }
            if (dx >= -1) {  // tap (dy,dx-1) of pos1
                float d = qr1[0] * k0.x + qr1[1] * k0.y + qr1[2] * k0.z + qr1[3] * k0.w +
                          qr1[4] * k1.x + qr1[5] * k1.y + qr1[6] * k1.z + qr1[7] * k1.w;
                d += __shfl_xor_sync(0xffffffffu, d, 1);
                d += __shfl_xor_sync(0xffffffffu, d, 2);
                d += __shfl_xor_sync(0xffffffffu, d, 4);
                const int j = (dy + 2) * 5 + dx + 1;
                if ((j & 7) == s) attp1[j >> 3] = d;
            }
        }

    // PE dots per position (bp cancels analytically)
    float a0 = 0.f, bq0 = 0.f, a1 = 0.f, bq1 = 0.f;
#pragma unroll
    for (int i = 0; i < 2; ++i)
#pragma unroll
        for (int j = 0; j < 4; ++j) {
            int ch = i * 32 + s * 4 + j;
            float2 w = __ldg((const float2*)wp + ch);
            a0 += qr0[i * 4 + j] * w.x; bq0 += qr0[i * 4 + j] * w.y;
            a1 += qr1[i * 4 + j] * w.x; bq1 += qr1[i * 4 + j] * w.y;
        }
#pragma unroll
    for (int st = 1; st < 8; st <<= 1) {
        a0 += __shfl_xor_sync(0xffffffffu, a0, st);
        bq0 += __shfl_xor_sync(0xffffffffu, bq0, st);
        a1 += __shfl_xor_sync(0xffffffffu, a1, st);
        bq1 += __shfl_xor_sync(0xffffffffu, bq1, st);
    }

    // phase 2: distributed softmax (lane s owns taps j%8==s), per position
    const float scaling = 0.125f;        // 64^-0.5
    const float lstep = 2.f / 55.f;
    const float r1 = rate1[0];
    const float r2 = rate2[0];

    float mx0 = -1e30f, mx1 = -1e30f;
#pragma unroll
    for (int i = 0; i < 4; ++i) {
        int j = s + 8 * i;
        if (j < 25) {
            int dy = j / 5 - 2, dx = j % 5 - 2;
            int gyj = refl(gy + dy);
            float t0 = scaling * (attp0[i] + a0 * ((float)(gx0 - refl(gx0 + dx)) * lstep) +
                                  bq0 * ((float)(gy - gyj) * lstep));
            float t1 = scaling * (attp1[i] + a1 * ((float)(gx1 - refl(gx1 + dx)) * lstep) +
                                  bq1 * ((float)(gy - gyj) * lstep));
            attp0[i] = t0; mx0 = fmaxf(mx0, t0);
            attp1[i] = t1; mx1 = fmaxf(mx1, t1);
        } else {
            attp0[i] = -1e30f;
            attp1[i] = -1e30f;
        }
    }
#pragma unroll
    for (int st = 1; st < 8; st <<= 1) {
        mx0 = fmaxf(mx0, __shfl_xor_sync(0xffffffffu, mx0, st));
        mx1 = fmaxf(mx1, __shfl_xor_sync(0xffffffffu, mx1, st));
    }
    float ss0 = 0.f, ss1 = 0.f;
#pragma unroll
    for (int i = 0; i < 4; ++i) {
        float e0 = __expf(attp0[i] - mx0); attp0[i] = e0; ss0 += e0;
        float e1 = __expf(attp1[i] - mx1); attp1[i] = e1; ss1 += e1;
    }
#pragma unroll
    for (int st = 1; st < 8; st <<= 1) {
        ss0 += __shfl_xor_sync(0xffffffffu, ss0, st);
        ss1 += __shfl_xor_sync(0xffffffffu, ss1, st);
    }
    const float c0n = r1 / ss0, c1n = r1 / ss1;
#pragma unroll
    for (int i = 0; i < 4; ++i) { attp0[i] *= c0n; attp1[i] *= c1n; }

    // phase 3: 30 v loads -> attention outputs for both positions + fused v-conv
    float oav0[8], oav1[8];
#pragma unroll
    for (int d = 0; d < 8; ++d) { oav0[d] = 0.f; oav1[d] = 0.f; }
#pragma unroll
    for (int dy = -2; dy <= 2; ++dy)
#pragma unroll
        for (int dx = -2; dx <= 3; ++dx) {
            const float* vb = vs + (chidx + dy * HALOW + dx) * PSTR + sb;
            float4 v0 = *(const float4*)(vb);
            float4 v1 = *(const float4*)(vb + 32);
            if (dx <= 2) {
                const int j = (dy + 2) * 5 + dx + 2;
                const float w = __shfl_sync(0xffffffffu, attp0[j >> 3], j & 7, 8);
                oav0[0] += w * v0.x; oav0[1] += w * v0.y;
                oav0[2] += w * v0.z; oav0[3] += w * v0.w;
                oav0[4] += w * v1.x; oav0[5] += w * v1.y;
                oav0[6] += w * v1.z; oav0[7] += w * v1.w;
            }
            if (dx >= -1) {
                const int j = (dy + 2) * 5 + dx + 1;
                const float w = __shfl_sync(0xffffffffu, attp1[j >> 3], j & 7, 8);
                oav1[0] += w * v0.x; oav1[1] += w * v0.y;
                oav1[2] += w * v0.z; oav1[3] += w * v0.w;
                oav1[4] += w * v1.x; oav1[5] += w * v1.y;
                oav1[6] += w * v1.z; oav1[7] += w * v1.w;
            }
            if (dy >= -1 && dy <= 1) {   // fused v-conv, zero padding
                if ((unsigned)(gy + dy) < 56u && (unsigned)(gx0 + dx) < 56u) {
                    if (dx >= -1 && dx <= 1) {
                        const float* wv = wfold + 1152 + ((dy + 1) * 3 + dx + 1) * 64 + sb;
                        float4 w0 = __ldg((const float4*)(wv));
                        float4 w1 = __ldg((const float4*)(wv + 32));
                        ocv0[0] += w0.x * v0.x; ocv0[1] += w0.y * v0.y;
                        ocv0[2] += w0.z * v0.z; ocv0[3] += w0.w * v0.w;
                        ocv0[4] += w1.x * v1.x; ocv0[5] += w1.y * v1.y;
                        ocv0[6] += w1.z * v1.z; ocv0[7] += w1.w * v1.w;
                    }
                    if (dx >= 0 && dx <= 2) {
                        const float* wv = wfold + 1152 + ((dy + 1) * 3 + dx) * 64 + sb;
                        float4 w0 = __ldg((const float4*)(wv));
                        float4 w1 = __ldg((const float4*)(wv + 32));
                        ocv1[0] += w0.x * v0.x; ocv1[1] += w0.y * v0.y;
                        ocv1[2] += w0.z * v0.z; ocv1[3] += w0.w * v0.w;
                        ocv1[4] += w1.x * v1.x; ocv1[5] += w1.y * v1.y;
                        ocv1[6] += w1.z * v1.z; ocv1[7] += w1.w * v1.w;
                    }
                }
            }
        }

#pragma unroll
    for (int i = 0; i < 2; ++i)
#pragma unroll
        for (int j = 0; j < 4; ++j) {
            int ch = i * 32 + s * 4 + j;
            float bd = __ldg(b_dep + ch);
            float2 res;
            res.x = oav0[i * 4 + j] + r2 * (ocv0[i * 4 + j] + bd);
            res.y = oav1[i * 4 + j] + r2 * (ocv1[i * 4 + j] + bd);
            *(float2*)(out + ((size_t)(b * 64 + ch) * 56 + gy) * 56 + gx0) = res;
        }
}

// ---------------- launch ----------------
extern "C" void kernel_launch(void* const* d_in, const int* in_sizes, int n_in,
                              void* d_out, int out_size) {
    const float* x    = (const float*)d_in[0];
    const float* w1   = (const float*)d_in[1];
    const float* b1   = (const float*)d_in[2];
    const float* w2   = (const float*)d_in[3];
    const float* b2   = (const float*)d_in[4];
    const float* w3   = (const float*)d_in[5];
    const float* b3   = (const float*)d_in[6];
    const float* wp   = (const float*)d_in[7];
    // d_in[8] = bp (cancels analytically)
    const float* w_fc = (const float*)d_in[9];
    const float* w_dep = (const float*)d_in[10];
    const float* b_dep = (const float*)d_in[11];
    const float* rate1 = (const float*)d_in[12];
    const float* rate2 = (const float*)d_in[13];
    float* out = (float*)d_out;

    const int qkv_smem = (4096 + 64 * WS_STRIDE + 192) * 4;
    const int att_smem = 2 * HALON * PSTR * 4;   // 73728 B
    cudaFuncSetAttribute(qkv_kernel, cudaFuncAttributeMaxDynamicSharedMemorySize, qkv_smem);
    cudaFuncSetAttribute(attn_kernel, cudaFuncAttributeMaxDynamicSharedMemorySize, att_smem);

    qkv_kernel<<<dim3(49, 8), 256, qkv_smem>>>(x, w1, b1, w2, b2, w3, b3, w_fc, w_dep);
    attn_kernel<<<dim3(7, 7, 8), 256, att_smem>>>(wp, b_dep, rate1, rate2, out);
}